// round 2
// baseline (speedup 1.0000x reference)
#include <cuda_runtime.h>
#include <cuda_bf16.h>
#include <cstdint>

// AWQ int4 linear: out[m][n] = sum_k x[m][k] * W[n][k] + bias[n]
//   W[n][k] = ( q[n][k] * scales[g] + offsets[g] ) * inv_scale[k],  g = n*32 + k/128
// Shapes: M=8192 (4*2048), N=OUT=11008, K=IN=4096, G=128.
//
// Strategy (round 1): SIMT tiled GEMM with packed f32x2 FMA (FFMA2), fused
// dequant into the B-tile smem store and inv_scale into the A-tile load.
// 128x128x16 CTA tile, 256 threads, 8x8 thread tile (held as 4x f32x2 pairs),
// double-buffered smem with register staging.

#define IN_DIM   4096
#define OUT_DIM  11008
#define M_DIM    8192
#define BM       128
#define BN       128
#define BK       16
#define KT       (IN_DIM / BK)      // 256 k-iterations
#define XSTR     (BM + 4)           // padded stride for transposed x tile
#define PK_ROW   (IN_DIM / 2)       // 2048 int32 per out-row
#define NG_ROW   (IN_DIM / 128)     // 32 groups per out-row

typedef unsigned long long ull;

__device__ __forceinline__ ull dup2(float v) {
    ull d;
    unsigned int r = __float_as_uint(v);
    asm("mov.b64 %0, {%1, %2};" : "=l"(d) : "r"(r), "r"(r));
    return d;
}

__device__ __forceinline__ ull ffma2(ull a, ull b, ull c) {
    ull d;
    asm("fma.rn.f32x2 %0, %1, %2, %3;" : "=l"(d) : "l"(a), "l"(b), "l"(c));
    return d;
}

__device__ __forceinline__ void unpack2(ull v, float& lo, float& hi) {
    unsigned int l, h;
    asm("mov.b64 {%0, %1}, %2;" : "=r"(l), "=r"(h) : "l"(v));
    lo = __uint_as_float(l);
    hi = __uint_as_float(h);
}

__global__ __launch_bounds__(256, 2)
void awq_gemm_kernel(const float* __restrict__ x,
                     const int*   __restrict__ packed,
                     const float* __restrict__ scales,
                     const float* __restrict__ offsets,
                     const float* __restrict__ inv_scale,
                     const float* __restrict__ bias,
                     float*       __restrict__ out) {
    __shared__ float xs[2][BK * XSTR];   // [k][m], padded
    __shared__ float ws[2][BK * BN];     // [k][n]

    const int tid   = threadIdx.x;
    const int ntile = blockIdx.x * BN;
    const int mtile = blockIdx.y * BM;

    // 16x16 thread grid over the 128x128 tile; each thread owns 8x8 outputs.
    const int tx = tid & 15;          // n direction
    const int ty = tid >> 4;          // m direction
    const int m0 = ty * 8;
    const int n0 = tx * 8;

    // --- staged-load assignments ---
    // x tile: 2048 floats; each thread loads two float4 rows (m and m+64), 4 k each.
    const int xm = tid >> 2;          // 0..63
    const int xk = (tid & 3) * 4;     // 0,4,8,12
    const float* xrow0 = x + (size_t)(mtile + xm) * IN_DIM + xk;
    const float* xrow1 = xrow0 + (size_t)64 * IN_DIM;

    // w tile: 128 rows x 8 int32 (16 k-values). Each thread: one row, int4 (4 packed).
    const int wn  = tid >> 1;         // 0..127
    const int wpb = (tid & 1) * 4;    // pair base 0 or 4
    const int*   prow = packed  + (size_t)(ntile + wn) * PK_ROW + wpb;
    const float* srow = scales  + (size_t)(ntile + wn) * NG_ROW;
    const float* orow = offsets + (size_t)(ntile + wn) * NG_ROW;

    ull acc[8][4];
#pragma unroll
    for (int i = 0; i < 8; ++i)
#pragma unroll
        for (int j = 0; j < 4; ++j) acc[i][j] = 0ull;

    // staged registers
    float4 sxa, sxb;
    int4   spk;
    float  ss, so;

    // ---- prologue: load k-block 0 ----
    {
        const float4 iv = *(const float4*)(inv_scale + xk);
        sxa = *(const float4*)(xrow0);
        sxb = *(const float4*)(xrow1);
        sxa.x *= iv.x; sxa.y *= iv.y; sxa.z *= iv.z; sxa.w *= iv.w;
        sxb.x *= iv.x; sxb.y *= iv.y; sxb.z *= iv.z; sxb.w *= iv.w;
        spk = *(const int4*)(prow);
        ss  = __ldg(srow);
        so  = __ldg(orow);
    }
    // store stage 0
    {
        float* xsb = xs[0];
        xsb[(xk + 0) * XSTR + xm] = sxa.x;
        xsb[(xk + 1) * XSTR + xm] = sxa.y;
        xsb[(xk + 2) * XSTR + xm] = sxa.z;
        xsb[(xk + 3) * XSTR + xm] = sxa.w;
        xsb[(xk + 0) * XSTR + xm + 64] = sxb.x;
        xsb[(xk + 1) * XSTR + xm + 64] = sxb.y;
        xsb[(xk + 2) * XSTR + xm + 64] = sxb.z;
        xsb[(xk + 3) * XSTR + xm + 64] = sxb.w;

        float* wsb = ws[0];
        const int pkv[4] = {spk.x, spk.y, spk.z, spk.w};
#pragma unroll
        for (int j = 0; j < 4; ++j) {
            const int u = pkv[j];
            const float lo = (float)(u & 15);
            const float hi = (float)((u >> 4) & 15);
            const int k = 2 * (wpb + j);
            wsb[(k + 0) * BN + wn] = fmaf(lo, ss, so);
            wsb[(k + 1) * BN + wn] = fmaf(hi, ss, so);
        }
    }
    __syncthreads();

    // ---- main loop ----
#pragma unroll 1
    for (int t = 0; t < KT; ++t) {
        const int cur  = t & 1;
        const bool more = (t + 1 < KT);

        if (more) {
            const int kb = (t + 1) * BK;
            const float4 iv = *(const float4*)(inv_scale + kb + xk);
            sxa = *(const float4*)(xrow0 + kb);
            sxb = *(const float4*)(xrow1 + kb);
            sxa.x *= iv.x; sxa.y *= iv.y; sxa.z *= iv.z; sxa.w *= iv.w;
            sxb.x *= iv.x; sxb.y *= iv.y; sxb.z *= iv.z; sxb.w *= iv.w;
            spk = *(const int4*)(prow + (kb >> 1));
            ss  = __ldg(srow + (kb >> 7));
            so  = __ldg(orow + (kb >> 7));
        }

        // compute on current buffer
        {
            const float* xsc = xs[cur];
            const float* wsc = ws[cur];
#pragma unroll
            for (int kk = 0; kk < BK; ++kk) {
                const float* xr = xsc + kk * XSTR;
                const ulonglong2* br =
                    (const ulonglong2*)(wsc + kk * BN + n0);
                const ulonglong2 b01 = br[0];
                const ulonglong2 b23 = br[1];
                const float4 a0 = *(const float4*)(xr + m0);
                const float4 a1 = *(const float4*)(xr + m0 + 4);
                const float av[8] = {a0.x, a0.y, a0.z, a0.w,
                                     a1.x, a1.y, a1.z, a1.w};
#pragma unroll
                for (int i = 0; i < 8; ++i) {
                    const ull ap = dup2(av[i]);
                    acc[i][0] = ffma2(ap, b01.x, acc[i][0]);
                    acc[i][1] = ffma2(ap, b01.y, acc[i][1]);
                    acc[i][2] = ffma2(ap, b23.x, acc[i][2]);
                    acc[i][3] = ffma2(ap, b23.y, acc[i][3]);
                }
            }
        }

        if (more) {
            const int nxt = (t + 1) & 1;
            float* xsb = xs[nxt];
            xsb[(xk + 0) * XSTR + xm] = sxa.x;
            xsb[(xk + 1) * XSTR + xm] = sxa.y;
            xsb[(xk + 2) * XSTR + xm] = sxa.z;
            xsb[(xk + 3) * XSTR + xm] = sxa.w;
            xsb[(xk + 0) * XSTR + xm + 64] = sxb.x;
            xsb[(xk + 1) * XSTR + xm + 64] = sxb.y;
            xsb[(xk + 2) * XSTR + xm + 64] = sxb.z;
            xsb[(xk + 3) * XSTR + xm + 64] = sxb.w;

            float* wsb = ws[nxt];
            const int pkv[4] = {spk.x, spk.y, spk.z, spk.w};
#pragma unroll
            for (int j = 0; j < 4; ++j) {
                const int u = pkv[j];
                const float lo = (float)(u & 15);
                const float hi = (float)((u >> 4) & 15);
                const int k = 2 * (wpb + j);
                wsb[(k + 0) * BN + wn] = fmaf(lo, ss, so);
                wsb[(k + 1) * BN + wn] = fmaf(hi, ss, so);
            }
        }
        __syncthreads();
    }

    // ---- epilogue: add bias, store ----
    float2 bj[4];
#pragma unroll
    for (int j = 0; j < 4; ++j)
        bj[j] = *(const float2*)(bias + ntile + n0 + 2 * j);

#pragma unroll
    for (int i = 0; i < 8; ++i) {
        float* orow_ = out + (size_t)(mtile + m0 + i) * OUT_DIM + ntile + n0;
#pragma unroll
        for (int j = 0; j < 4; ++j) {
            float lo, hi;
            unpack2(acc[i][j], lo, hi);
            float2 v;
            v.x = lo + bj[j].x;
            v.y = hi + bj[j].y;
            *(float2*)(orow_ + 2 * j) = v;
        }
    }
}

extern "C" void kernel_launch(void* const* d_in, const int* in_sizes, int n_in,
                              void* d_out, int out_size) {
    const float* x         = (const float*)d_in[0];
    const int*   packed    = (const int*)  d_in[1];
    const float* scales    = (const float*)d_in[2];
    const float* offsets   = (const float*)d_in[3];
    const float* inv_scale = (const float*)d_in[4];
    const float* bias      = (const float*)d_in[5];
    float*       out       = (float*)d_out;

    dim3 grid(OUT_DIM / BN, M_DIM / BM);   // (86, 64)
    dim3 block(256);
    awq_gemm_kernel<<<grid, block>>>(x, packed, scales, offsets,
                                     inv_scale, bias, out);
}

// round 4
// speedup vs baseline: 3.3980x; 3.3980x over previous
#include <cuda_runtime.h>
#include <cstdint>

// ============================================================================
// AWQ int4 linear via generic-target tensor cores (mma.sync tf32):
//   (1) dequant W -> tf32 in fragment-order tiles  (inv_scale folded in)
//   (2) round x  -> tf32 in fragment-order tiles
//   (3) GEMM: 128x128 CTA tiles, warp 64x32, m16n8k8 tf32 mma.sync,
//       6-stage cp.async pipeline, conflict-free LDS.128 fragment loads.
// out[m][n] = sum_k x[m][k]*W[n][k] + bias[n]
// W[n][k] = (q[n][k]*scales[g]+offsets[g])*inv_scale[k], g = n*32 + k/128
// M=8192, N=11008, K=4096.
// ============================================================================

#define IN_DIM   4096
#define OUT_DIM  11008
#define M_DIM    8192
#define BKC      16                    // k per pipeline stage
#define NKC      (IN_DIM / BKC)        // 256 k-chunks
#define STAGES   6
#define TILE_FLOATS 2048               // one 128x16 operand tile
#define STAGE_FLOATS (2 * TILE_FLOATS) // A tile then B tile
#define SMEM_BYTES (STAGES * STAGE_FLOATS * 4)   // 98304
#define MT_TILES  (M_DIM / 128)        // 64
#define NT_TILES  ((OUT_DIM + 127) / 128)  // 86

// Pre-tiled tf32 operands in fragment order (static scratch; no allocs).
__device__ float g_w[(size_t)NT_TILES * NKC * TILE_FLOATS];
__device__ float g_x[(size_t)MT_TILES * NKC * TILE_FLOATS];

__device__ __forceinline__ float to_tf32(float f) {
    float r;
    asm("cvt.rna.tf32.f32 %0, %1;" : "=f"(r) : "f"(f));
    return r;
}

__device__ __forceinline__ uint32_t smem_u32(const void* p) {
    uint32_t a;
    asm("{ .reg .u64 t; cvta.to.shared.u64 t, %1; cvt.u32.u64 %0, t; }"
        : "=r"(a) : "l"(p));
    return a;
}

// Fragment-order offsets within a 2048-float (128 x 16) tile.
// A (x) tile: mm in [0,128), kk16 in [0,16):
//   wm=mm>>6, b=(mm>>4)&3, gid=mm&7, hi=(mm>>3)&1
//   kk=(kk16>>3)&1, c=(kk16>>2)&1, tig=kk16&3
//   vec v = kk*4+b; lane = gid*4+tig; slot = hi+2*c
__device__ __forceinline__ int a_off(int mm, int kk16) {
    const int wm = mm >> 6, b = (mm >> 4) & 3, gid = mm & 7, hi = (mm >> 3) & 1;
    const int kk = (kk16 >> 3) & 1, c = (kk16 >> 2) & 1, tig = kk16 & 3;
    return ((wm * 8 + kk * 4 + b) * 32 + gid * 4 + tig) * 4 + hi + 2 * c;
}
// B (W) tile: nn in [0,128), kk16 in [0,16):
//   wn=nn>>5, nb=(nn>>3)&3, g=nn&7; kk=(kk16>>3)&1, h=(kk16>>2)&1, tig=kk16&3
//   vec = nb; lane = g*4+tig; slot = kk*2+h
__device__ __forceinline__ int b_off(int nn, int kk16) {
    const int wn = nn >> 5, nb = (nn >> 3) & 3, g = nn & 7;
    const int kk = (kk16 >> 3) & 1, h = (kk16 >> 2) & 1, tig = kk16 & 3;
    return ((wn * 4 + nb) * 32 + g * 4 + tig) * 4 + kk * 2 + h;
}

// ============================================================================
// Prepass 1: dequant W -> tf32 fragment tiles. One thread per packed int32.
// ============================================================================
__global__ __launch_bounds__(256)
void dequant_w_kernel(const int* __restrict__ packed,
                      const float* __restrict__ scales,
                      const float* __restrict__ offsets,
                      const float* __restrict__ inv) {
    const int j = blockIdx.x * 256 + threadIdx.x;
    const int n  = j >> 11;               // 2048 int32 per out-row
    const int k0 = (j & 2047) * 2;
    const int u = packed[j];
    const int g = (n << 5) + (k0 >> 7);
    const float s = __ldg(scales + g);
    const float o = __ldg(offsets + g);
    const float w0 = fmaf((float)(u & 15), s, o) * __ldg(inv + k0);
    const float w1 = fmaf((float)((u >> 4) & 15), s, o) * __ldg(inv + k0 + 1);

    const int nT = n >> 7, nn = n & 127, kc = k0 >> 4, kk16 = k0 & 15;
    float* base = g_w + ((size_t)nT * NKC + kc) * TILE_FLOATS;
    base[b_off(nn, kk16)]     = to_tf32(w0);
    base[b_off(nn, kk16 + 1)] = to_tf32(w1);
}

// ============================================================================
// Prepass 2: x -> tf32 fragment tiles. One thread per float2.
// ============================================================================
__global__ __launch_bounds__(256)
void prep_x_kernel(const float* __restrict__ x) {
    const int j = blockIdx.x * 256 + threadIdx.x;
    const int m  = j >> 11;
    const int k0 = (j & 2047) * 2;
    const float2 xv = *(const float2*)(x + (size_t)m * IN_DIM + k0);

    const int mT = m >> 7, mm = m & 127, kc = k0 >> 4, kk16 = k0 & 15;
    float* base = g_x + ((size_t)mT * NKC + kc) * TILE_FLOATS;
    base[a_off(mm, kk16)]     = to_tf32(xv.x);
    base[a_off(mm, kk16 + 1)] = to_tf32(xv.y);
}

// ============================================================================
// Main GEMM
// ============================================================================
#define MMA_TF32(c, a, b0v, b1v)                                               \
    asm volatile("mma.sync.aligned.m16n8k8.row.col.f32.tf32.tf32.f32 "         \
        "{%0,%1,%2,%3}, {%4,%5,%6,%7}, {%8,%9}, {%0,%1,%2,%3};"                \
        : "+f"((c)[0]), "+f"((c)[1]), "+f"((c)[2]), "+f"((c)[3])               \
        : "r"(__float_as_uint((a).x)), "r"(__float_as_uint((a).y)),            \
          "r"(__float_as_uint((a).z)), "r"(__float_as_uint((a).w)),            \
          "r"(__float_as_uint(b0v)), "r"(__float_as_uint(b1v)))

#define CP_ASYNC16(dst, src)                                                   \
    asm volatile("cp.async.cg.shared.global [%0], [%1], 16;"                   \
                 :: "r"(dst), "l"(src) : "memory")
#define CP_COMMIT()  asm volatile("cp.async.commit_group;" ::: "memory")
#define CP_WAIT4()   asm volatile("cp.async.wait_group 4;" ::: "memory")

__global__ __launch_bounds__(256, 1)
void awq_mma_gemm(const float* __restrict__ bias, float* __restrict__ out) {
    extern __shared__ float sm[];
    const int tid  = threadIdx.x;
    const int wid  = tid >> 5;
    const int lane = tid & 31;
    const int wm   = wid >> 2;      // 0..1 (m 64-half)
    const int wn   = wid & 3;       // 0..3 (n 32-quarter)

    // supertile raster: grid(256, 22); x: 8 nT x 32 mT inside a supertile
    const int sc  = blockIdx.y % 11;      // supercolumn (8 nT each)
    const int smr = blockIdx.y / 11;      // superrow (32 mT each)
    const int nT  = sc * 8 + (blockIdx.x & 7);
    const int mT  = smr * 32 + (blockIdx.x >> 3);
    if (nT >= NT_TILES) return;

    const float* aSrc = g_x + (size_t)mT * NKC * TILE_FLOATS;
    const float* bSrc = g_w + (size_t)nT * NKC * TILE_FLOATS;
    const uint32_t sb = smem_u32(sm);

    float acc[4][4][4];
#pragma unroll
    for (int b = 0; b < 4; ++b)
#pragma unroll
        for (int nb = 0; nb < 4; ++nb)
#pragma unroll
            for (int i = 0; i < 4; ++i) acc[b][nb][i] = 0.0f;

    // ---- pipeline prologue: load chunks 0..STAGES-2 ----
#pragma unroll
    for (int s = 0; s < STAGES - 1; ++s) {
        const uint32_t dst = sb + s * STAGE_FLOATS * 4;
#pragma unroll
        for (int i = 0; i < 4; ++i) {
            const int f = i * 256 + tid;        // float4 index, 0..1023
            const float* src = (f < 512)
                ? (aSrc + (size_t)s * TILE_FLOATS + f * 4)
                : (bSrc + (size_t)s * TILE_FLOATS + (f - 512) * 4);
            CP_ASYNC16(dst + f * 16, src);
        }
        CP_COMMIT();
    }

    int stage = 0, pf_stage = STAGES - 1;
#pragma unroll 1
    for (int kc = 0; kc < NKC; ++kc) {
        CP_WAIT4();              // chunk kc resident
        __syncthreads();         // and everyone done with stage being refilled

        // prefetch chunk kc+STAGES-1
        if (kc + STAGES - 1 < NKC) {
            const int pc = kc + STAGES - 1;
            const uint32_t dst = sb + pf_stage * STAGE_FLOATS * 4;
#pragma unroll
            for (int i = 0; i < 4; ++i) {
                const int f = i * 256 + tid;
                const float* src = (f < 512)
                    ? (aSrc + (size_t)pc * TILE_FLOATS + f * 4)
                    : (bSrc + (size_t)pc * TILE_FLOATS + (f - 512) * 4);
                CP_ASYNC16(dst + f * 16, src);
            }
        }
        CP_COMMIT();
        if (++pf_stage == STAGES) pf_stage = 0;

        // ---- compute chunk kc ----
        const float* As = sm + stage * STAGE_FLOATS;
        const float* Bs = As + TILE_FLOATS;

        float4 Af[8], Bf[4];
#pragma unroll
        for (int v = 0; v < 8; ++v)
            Af[v] = *(const float4*)(As + ((wm * 8 + v) * 32 + lane) * 4);
#pragma unroll
        for (int nb = 0; nb < 4; ++nb)
            Bf[nb] = *(const float4*)(Bs + ((wn * 4 + nb) * 32 + lane) * 4);

#pragma unroll
        for (int kk = 0; kk < 2; ++kk) {
#pragma unroll
            for (int b = 0; b < 4; ++b) {
                const float4 a = Af[kk * 4 + b];
#pragma unroll
                for (int nb = 0; nb < 4; ++nb) {
                    const float b0v = (kk == 0) ? Bf[nb].x : Bf[nb].z;
                    const float b1v = (kk == 0) ? Bf[nb].y : Bf[nb].w;
                    MMA_TF32(acc[b][nb], a, b0v, b1v);
                }
            }
        }
        if (++stage == STAGES) stage = 0;
    }

    // ---- epilogue: bias + store ----
    const int gid = lane >> 2, tig = lane & 3;
    const int m0 = mT * 128 + wm * 64;
    const int n0 = nT * 128 + wn * 32;
#pragma unroll
    for (int nb = 0; nb < 4; ++nb) {
        const int n = n0 + nb * 8 + tig * 2;
        const float2 bv = *(const float2*)(bias + n);
#pragma unroll
        for (int b = 0; b < 4; ++b) {
            const int mA = m0 + b * 16 + gid;
            float2 v0, v1;
            v0.x = acc[b][nb][0] + bv.x;
            v0.y = acc[b][nb][1] + bv.y;
            v1.x = acc[b][nb][2] + bv.x;
            v1.y = acc[b][nb][3] + bv.y;
            *(float2*)(out + (size_t)mA * OUT_DIM + n) = v0;
            *(float2*)(out + (size_t)(mA + 8) * OUT_DIM + n) = v1;
        }
    }
}

// ============================================================================
extern "C" void kernel_launch(void* const* d_in, const int* in_sizes, int n_in,
                              void* d_out, int out_size) {
    const float* x         = (const float*)d_in[0];
    const int*   packed    = (const int*)  d_in[1];
    const float* scales    = (const float*)d_in[2];
    const float* offsets   = (const float*)d_in[3];
    const float* inv_scale = (const float*)d_in[4];
    const float* bias      = (const float*)d_in[5];
    float*       out       = (float*)d_out;

    static bool attr_set = false;
    if (!attr_set) {
        cudaFuncSetAttribute(awq_mma_gemm,
                             cudaFuncAttributeMaxDynamicSharedMemorySize,
                             SMEM_BYTES);
        attr_set = true;
    }

    dequant_w_kernel<<<(OUT_DIM * (IN_DIM / 2)) / 256, 256>>>(packed, scales,
                                                              offsets, inv_scale);
    prep_x_kernel<<<(M_DIM * (IN_DIM / 2)) / 256, 256>>>(x);

    dim3 grid(256, 22);   // 8 nT x 32 mT supertiles; 2 superrows x 11 supercols
    awq_mma_gemm<<<grid, 256, SMEM_BYTES>>>(bias, out);
}

// round 5
// speedup vs baseline: 7.2582x; 2.1360x over previous
#include <cuda_runtime.h>
#include <cuda_fp16.h>
#include <cstdint>

// ============================================================================
// AWQ int4 linear via fp16 mma.sync (m16n8k16, fp32 accumulate):
//   (1) dequant W -> fp16 fragment-order tiles (inv_scale folded in)
//   (2) round x  -> fp16 fragment-order tiles
//   (3) GEMM: 128x128 CTA tiles, warp 64x32, k-chunk 32,
//       6-stage cp.async pipeline, conflict-free LDS.128 fragment loads.
// fp16 has the same 10-bit mantissa as tf32 (R4 rel_err 2.96e-4) but legacy
// HMMA fp16 runs at 2x the tf32 rate and halves all operand traffic.
// out[m][n] = sum_k x[m][k]*W[n][k] + bias[n]
// W[n][k] = (q[n][k]*scales[g]+offsets[g])*inv_scale[k], g = n*32 + k/128
// M=8192, N=11008, K=4096.
// ============================================================================

#define IN_DIM   4096
#define OUT_DIM  11008
#define M_DIM    8192
#define BKC      32                    // k per pipeline stage
#define NKC      (IN_DIM / BKC)        // 128 k-chunks
#define STAGES   6
#define TILE_U32 2048                  // one 128x32 fp16 operand tile (8KB)
#define STAGE_U32 (2 * TILE_U32)       // A tile then B tile (16KB)
#define SMEM_BYTES (STAGES * STAGE_U32 * 4)   // 98304
#define MT_TILES  (M_DIM / 128)        // 64
#define NT_TILES  (OUT_DIM / 128)      // 86

// Pre-tiled fp16 operands in fragment order (static scratch; no allocs).
__device__ uint32_t g_w[(size_t)NT_TILES * NKC * TILE_U32];   // 90 MB
__device__ uint32_t g_x[(size_t)MT_TILES * NKC * TILE_U32];   // 67 MB

__device__ __forceinline__ uint32_t smem_u32(const void* p) {
    uint32_t a;
    asm("{ .reg .u64 t; cvta.to.shared.u64 t, %1; cvt.u32.u64 %0, t; }"
        : "=r"(a) : "l"(p));
    return a;
}

// ---- fragment-order u32 offsets within a 2048-u32 (128 x 32 fp16) tile ----
// A (x) element (mm in [0,128), kk in [0,32)), kk even pairs share one u32.
//   m16n8k16 A frag: a0={row g, col 2t..+1}, a1={row g+8, same}, a2={g, col+8},
//   a3={g+8, col+8}. Lane float4 per (wm,ks,b) tile at vec index wm*8+ks*4+b.
__device__ __forceinline__ int a_u32(int mm, int kk) {
    const int wm = mm >> 6, b = (mm >> 4) & 3, row = mm & 15;
    const int gid = row & 7, hi = row >> 3;
    const int ks = kk >> 4, kk16 = kk & 15;
    const int colhi = (kk16 >> 3) & 1, tig = (kk16 >> 1) & 3;
    const int v = wm * 8 + ks * 4 + b;
    return (v * 32 + gid * 4 + tig) * 4 + hi + 2 * colhi;
}
// B (W) element (nn in [0,128), kk in [0,32)).
//   B frag: b0={rows 2t..+1, col g}, b1={rows 2t+8..+9, col g}.
//   Lane holds 2 float4 per (wn,ks): [nb0.b0,nb0.b1,nb1.b0,nb1.b1], [nb2..nb3].
__device__ __forceinline__ int b_u32(int nn, int kk) {
    const int wn = nn >> 5, nb = (nn >> 3) & 3, gid = nn & 7;
    const int ks = kk >> 4, kk16 = kk & 15;
    const int khi = (kk16 >> 3) & 1, tig = (kk16 >> 1) & 3;
    return ((((wn * 2 + ks) * 2 + (nb >> 1)) * 32) + gid * 4 + tig) * 4
           + (nb & 1) * 2 + khi;
}

__device__ __forceinline__ uint32_t pack_h2(float lo, float hi) {
    __half2 h = __floats2half2_rn(lo, hi);   // .x = lo half
    return *(uint32_t*)&h;
}

// ============================================================================
// Prepass 1: dequant W -> fp16 fragment tiles. One thread per packed int32.
// ============================================================================
__global__ __launch_bounds__(256)
void dequant_w_kernel(const int* __restrict__ packed,
                      const float* __restrict__ scales,
                      const float* __restrict__ offsets,
                      const float* __restrict__ inv) {
    const int j = blockIdx.x * 256 + threadIdx.x;
    const int n  = j >> 11;               // 2048 int32 per out-row
    const int k0 = (j & 2047) * 2;        // even
    const int u = packed[j];
    const int g = (n << 5) + (k0 >> 7);
    const float s = __ldg(scales + g);
    const float o = __ldg(offsets + g);
    const float w0 = fmaf((float)(u & 15), s, o) * __ldg(inv + k0);
    const float w1 = fmaf((float)((u >> 4) & 15), s, o) * __ldg(inv + k0 + 1);

    const int nT = n >> 7, nn = n & 127, kc = k0 >> 5, kk = k0 & 31;
    uint32_t* base = g_w + ((size_t)nT * NKC + kc) * TILE_U32;
    base[b_u32(nn, kk)] = pack_h2(w0, w1);
}

// ============================================================================
// Prepass 2: x -> fp16 fragment tiles. One thread per float2.
// ============================================================================
__global__ __launch_bounds__(256)
void prep_x_kernel(const float* __restrict__ x) {
    const int j = blockIdx.x * 256 + threadIdx.x;
    const int m  = j >> 11;
    const int k0 = (j & 2047) * 2;
    const float2 xv = *(const float2*)(x + (size_t)m * IN_DIM + k0);

    const int mT = m >> 7, mm = m & 127, kc = k0 >> 5, kk = k0 & 31;
    uint32_t* base = g_x + ((size_t)mT * NKC + kc) * TILE_U32;
    base[a_u32(mm, kk)] = pack_h2(xv.x, xv.y);
}

// ============================================================================
// Main GEMM
// ============================================================================
#define MMA_F16(c, a, b0v, b1v)                                                \
    asm volatile("mma.sync.aligned.m16n8k16.row.col.f32.f16.f16.f32 "          \
        "{%0,%1,%2,%3}, {%4,%5,%6,%7}, {%8,%9}, {%0,%1,%2,%3};"                \
        : "+f"((c)[0]), "+f"((c)[1]), "+f"((c)[2]), "+f"((c)[3])               \
        : "r"((a).x), "r"((a).y), "r"((a).z), "r"((a).w),                      \
          "r"(b0v), "r"(b1v))

#define CP_ASYNC16(dst, src)                                                   \
    asm volatile("cp.async.cg.shared.global [%0], [%1], 16;"                   \
                 :: "r"(dst), "l"(src) : "memory")
#define CP_COMMIT()  asm volatile("cp.async.commit_group;" ::: "memory")
#define CP_WAIT4()   asm volatile("cp.async.wait_group 4;" ::: "memory")

__global__ __launch_bounds__(256, 1)
void awq_mma_gemm(const float* __restrict__ bias, float* __restrict__ out) {
    extern __shared__ uint32_t sm[];
    const int tid  = threadIdx.x;
    const int wid  = tid >> 5;
    const int lane = tid & 31;
    const int wm   = wid >> 2;      // 0..1 (m 64-half)
    const int wn   = wid & 3;       // 0..3 (n 32-quarter)

    // supertile raster: grid(256, 22); x: 8 nT x 32 mT inside a supertile
    const int sc  = blockIdx.y % 11;      // supercolumn (8 nT each)
    const int smr = blockIdx.y / 11;      // superrow (32 mT each)
    const int nT  = sc * 8 + (blockIdx.x & 7);
    const int mT  = smr * 32 + (blockIdx.x >> 3);
    if (nT >= NT_TILES) return;

    const uint32_t* aSrc = g_x + (size_t)mT * NKC * TILE_U32;
    const uint32_t* bSrc = g_w + (size_t)nT * NKC * TILE_U32;
    const uint32_t sb = smem_u32(sm);

    float acc[4][4][4];
#pragma unroll
    for (int b = 0; b < 4; ++b)
#pragma unroll
        for (int nb = 0; nb < 4; ++nb)
#pragma unroll
            for (int i = 0; i < 4; ++i) acc[b][nb][i] = 0.0f;

    // ---- pipeline prologue: load chunks 0..STAGES-2 ----
#pragma unroll
    for (int s = 0; s < STAGES - 1; ++s) {
        const uint32_t dst = sb + s * STAGE_U32 * 4;
#pragma unroll
        for (int i = 0; i < 4; ++i) {
            const int f = i * 256 + tid;        // uint4 index, 0..1023
            const uint32_t* src = (f < 512)
                ? (aSrc + (size_t)s * TILE_U32 + f * 4)
                : (bSrc + (size_t)s * TILE_U32 + (f - 512) * 4);
            CP_ASYNC16(dst + f * 16, src);
        }
        CP_COMMIT();
    }

    int stage = 0, pf_stage = STAGES - 1;
#pragma unroll 1
    for (int kc = 0; kc < NKC; ++kc) {
        CP_WAIT4();              // chunk kc resident
        __syncthreads();         // and everyone done with stage being refilled

        // prefetch chunk kc+STAGES-1
        if (kc + STAGES - 1 < NKC) {
            const int pc = kc + STAGES - 1;
            const uint32_t dst = sb + pf_stage * STAGE_U32 * 4;
#pragma unroll
            for (int i = 0; i < 4; ++i) {
                const int f = i * 256 + tid;
                const uint32_t* src = (f < 512)
                    ? (aSrc + (size_t)pc * TILE_U32 + f * 4)
                    : (bSrc + (size_t)pc * TILE_U32 + (f - 512) * 4);
                CP_ASYNC16(dst + f * 16, src);
            }
        }
        CP_COMMIT();
        if (++pf_stage == STAGES) pf_stage = 0;

        // ---- compute chunk kc (k=32 = 2 k16-steps) ----
        const uint32_t* As = sm + stage * STAGE_U32;
        const uint32_t* Bs = As + TILE_U32;

        uint4 Af[2][4], Bf[2][2];
#pragma unroll
        for (int ks = 0; ks < 2; ++ks) {
#pragma unroll
            for (int b = 0; b < 4; ++b)
                Af[ks][b] = *(const uint4*)
                    (As + ((wm * 8 + ks * 4 + b) * 32 + lane) * 4);
#pragma unroll
            for (int p = 0; p < 2; ++p)
                Bf[ks][p] = *(const uint4*)
                    (Bs + ((((wn * 2 + ks) * 2 + p) * 32) + lane) * 4);
        }

#pragma unroll
        for (int ks = 0; ks < 2; ++ks) {
#pragma unroll
            for (int b = 0; b < 4; ++b) {
                const uint4 a = Af[ks][b];
#pragma unroll
                for (int nb = 0; nb < 4; ++nb) {
                    const uint4 bf = Bf[ks][nb >> 1];
                    const uint32_t b0v = (nb & 1) ? bf.z : bf.x;
                    const uint32_t b1v = (nb & 1) ? bf.w : bf.y;
                    MMA_F16(acc[b][nb], a, b0v, b1v);
                }
            }
        }
        if (++stage == STAGES) stage = 0;
    }

    // ---- epilogue: bias + store ----
    const int gid = lane >> 2, tig = lane & 3;
    const int m0 = mT * 128 + wm * 64;
    const int n0 = nT * 128 + wn * 32;
#pragma unroll
    for (int nb = 0; nb < 4; ++nb) {
        const int n = n0 + nb * 8 + tig * 2;
        const float2 bv = *(const float2*)(bias + n);
#pragma unroll
        for (int b = 0; b < 4; ++b) {
            const int mA = m0 + b * 16 + gid;
            float2 v0, v1;
            v0.x = acc[b][nb][0] + bv.x;
            v0.y = acc[b][nb][1] + bv.y;
            v1.x = acc[b][nb][2] + bv.x;
            v1.y = acc[b][nb][3] + bv.y;
            *(float2*)(out + (size_t)mA * OUT_DIM + n) = v0;
            *(float2*)(out + (size_t)(mA + 8) * OUT_DIM + n) = v1;
        }
    }
}

// ============================================================================
extern "C" void kernel_launch(void* const* d_in, const int* in_sizes, int n_in,
                              void* d_out, int out_size) {
    const float* x         = (const float*)d_in[0];
    const int*   packed    = (const int*)  d_in[1];
    const float* scales    = (const float*)d_in[2];
    const float* offsets   = (const float*)d_in[3];
    const float* inv_scale = (const float*)d_in[4];
    const float* bias      = (const float*)d_in[5];
    float*       out       = (float*)d_out;

    static bool attr_set = false;
    if (!attr_set) {
        cudaFuncSetAttribute(awq_mma_gemm,
                             cudaFuncAttributeMaxDynamicSharedMemorySize,
                             SMEM_BYTES);
        attr_set = true;
    }

    dequant_w_kernel<<<(OUT_DIM * (IN_DIM / 2)) / 256, 256>>>(packed, scales,
                                                              offsets, inv_scale);
    prep_x_kernel<<<(M_DIM * (IN_DIM / 2)) / 256, 256>>>(x);

    dim3 grid(256, 22);   // 8 nT x 32 mT supertiles; 2 superrows x 11 supercols
    awq_mma_gemm<<<grid, 256, SMEM_BYTES>>>(bias, out);
}

// round 6
// speedup vs baseline: 9.0892x; 1.2523x over previous
#include <cuda_runtime.h>
#include <cuda_fp16.h>
#include <cstdint>

// ============================================================================
// AWQ int4 linear via fp16 mma.sync (m16n8k16, fp32 accumulate):
//   (1) dequant W -> fp16 fragment-order tiles (inv_scale folded in)
//   (2) round x  -> fp16 fragment-order tiles
//   (3) GEMM: 128x128 CTA tiles, warp 64x32, k-chunk 32,
//       4-stage cp.async pipeline, 2 CTAs/SM, conflict-free LDS.128 loads.
// out[m][n] = sum_k x[m][k]*W[n][k] + bias[n]
// W[n][k] = (q[n][k]*scales[g]+offsets[g])*inv_scale[k], g = n*32 + k/128
// M=8192, N=11008, K=4096.
// ============================================================================

#define IN_DIM   4096
#define OUT_DIM  11008
#define M_DIM    8192
#define BKC      32                    // k per pipeline stage
#define NKC      (IN_DIM / BKC)        // 128 k-chunks
#define STAGES   4
#define TILE_U32 2048                  // one 128x32 fp16 operand tile (8KB)
#define STAGE_U32 (2 * TILE_U32)       // A tile then B tile (16KB)
#define SMEM_BYTES (STAGES * STAGE_U32 * 4)   // 65536
#define MT_TILES  (M_DIM / 128)        // 64
#define NT_TILES  (OUT_DIM / 128)      // 86

// Pre-tiled fp16 operands in fragment order (static scratch; no allocs).
__device__ uint32_t g_w[(size_t)NT_TILES * NKC * TILE_U32];   // 90 MB
__device__ uint32_t g_x[(size_t)MT_TILES * NKC * TILE_U32];   // 67 MB

__device__ __forceinline__ uint32_t smem_u32(const void* p) {
    uint32_t a;
    asm("{ .reg .u64 t; cvta.to.shared.u64 t, %1; cvt.u32.u64 %0, t; }"
        : "=r"(a) : "l"(p));
    return a;
}

// ---- fragment-order u32 offsets within a 2048-u32 (128 x 32 fp16) tile ----
__device__ __forceinline__ int a_u32(int mm, int kk) {
    const int wm = mm >> 6, b = (mm >> 4) & 3, row = mm & 15;
    const int gid = row & 7, hi = row >> 3;
    const int ks = kk >> 4, kk16 = kk & 15;
    const int colhi = (kk16 >> 3) & 1, tig = (kk16 >> 1) & 3;
    const int v = wm * 8 + ks * 4 + b;
    return (v * 32 + gid * 4 + tig) * 4 + hi + 2 * colhi;
}
__device__ __forceinline__ int b_u32(int nn, int kk) {
    const int wn = nn >> 5, nb = (nn >> 3) & 3, gid = nn & 7;
    const int ks = kk >> 4, kk16 = kk & 15;
    const int khi = (kk16 >> 3) & 1, tig = (kk16 >> 1) & 3;
    return ((((wn * 2 + ks) * 2 + (nb >> 1)) * 32) + gid * 4 + tig) * 4
           + (nb & 1) * 2 + khi;
}

__device__ __forceinline__ uint32_t pack_h2(float lo, float hi) {
    __half2 h = __floats2half2_rn(lo, hi);   // .x = lo half
    return *(uint32_t*)&h;
}

// ============================================================================
// Prepass 1: dequant W -> fp16 fragment tiles. 4 packed u32 (8 w) per thread.
// ============================================================================
__global__ __launch_bounds__(256)
void dequant_w_kernel(const int* __restrict__ packed,
                      const float* __restrict__ scales,
                      const float* __restrict__ offsets,
                      const float* __restrict__ inv) {
    const int j0 = (blockIdx.x * 256 + threadIdx.x) * 4;
    const int n  = j0 >> 11;               // 2048 int32 per out-row
    const int k0 = (j0 & 2047) * 2;        // multiple of 8; 8 k's same group
    const int4 u4 = *(const int4*)(packed + j0);
    const int g = (n << 5) + (k0 >> 7);
    const float s = __ldg(scales + g);
    const float o = __ldg(offsets + g);
    const float4 iv0 = *(const float4*)(inv + k0);
    const float4 iv1 = *(const float4*)(inv + k0 + 4);
    const float ivv[8] = {iv0.x, iv0.y, iv0.z, iv0.w,
                          iv1.x, iv1.y, iv1.z, iv1.w};
    const int uv[4] = {u4.x, u4.y, u4.z, u4.w};

    const int nT = n >> 7, nn = n & 127, kc = k0 >> 5;
    uint32_t* base = g_w + ((size_t)nT * NKC + kc) * TILE_U32;
#pragma unroll
    for (int i = 0; i < 4; ++i) {
        const int u = uv[i];
        const float w0 = fmaf((float)(u & 15), s, o) * ivv[2 * i];
        const float w1 = fmaf((float)((u >> 4) & 15), s, o) * ivv[2 * i + 1];
        base[b_u32(nn, (k0 & 31) + 2 * i)] = pack_h2(w0, w1);
    }
}

// ============================================================================
// Prepass 2: x -> fp16 fragment tiles. 8 consecutive k per thread.
// ============================================================================
__global__ __launch_bounds__(256)
void prep_x_kernel(const float* __restrict__ x) {
    const int j0 = (blockIdx.x * 256 + threadIdx.x) * 4;   // float2 index
    const int m  = j0 >> 11;
    const int k0 = (j0 & 2047) * 2;        // multiple of 8
    const float4 v0 = *(const float4*)(x + (size_t)m * IN_DIM + k0);
    const float4 v1 = *(const float4*)(x + (size_t)m * IN_DIM + k0 + 4);

    const int mT = m >> 7, mm = m & 127, kc = k0 >> 5, kk = k0 & 31;
    uint32_t* base = g_x + ((size_t)mT * NKC + kc) * TILE_U32;
    base[a_u32(mm, kk + 0)] = pack_h2(v0.x, v0.y);
    base[a_u32(mm, kk + 2)] = pack_h2(v0.z, v0.w);
    base[a_u32(mm, kk + 4)] = pack_h2(v1.x, v1.y);
    base[a_u32(mm, kk + 6)] = pack_h2(v1.z, v1.w);
}

// ============================================================================
// Main GEMM
// ============================================================================
#define MMA_F16(c, a, b0v, b1v)                                                \
    asm volatile("mma.sync.aligned.m16n8k16.row.col.f32.f16.f16.f32 "          \
        "{%0,%1,%2,%3}, {%4,%5,%6,%7}, {%8,%9}, {%0,%1,%2,%3};"                \
        : "+f"((c)[0]), "+f"((c)[1]), "+f"((c)[2]), "+f"((c)[3])               \
        : "r"((a).x), "r"((a).y), "r"((a).z), "r"((a).w),                      \
          "r"(b0v), "r"(b1v))

#define CP_ASYNC16(dst, src)                                                   \
    asm volatile("cp.async.cg.shared.global [%0], [%1], 16;"                   \
                 :: "r"(dst), "l"(src) : "memory")
#define CP_COMMIT()  asm volatile("cp.async.commit_group;" ::: "memory")
#define CP_WAIT2()   asm volatile("cp.async.wait_group 2;" ::: "memory")

__global__ __launch_bounds__(256, 2)
void awq_mma_gemm(const float* __restrict__ bias, float* __restrict__ out) {
    extern __shared__ uint32_t sm[];
    const int tid  = threadIdx.x;
    const int wid  = tid >> 5;
    const int lane = tid & 31;
    const int wm   = wid >> 2;      // 0..1 (m 64-half)
    const int wn   = wid & 3;       // 0..3 (n 32-quarter)

    // supertile raster: grid(256, 22); x: 8 nT x 32 mT inside a supertile
    const int sc  = blockIdx.y % 11;      // supercolumn (8 nT each)
    const int smr = blockIdx.y / 11;      // superrow (32 mT each)
    const int nT  = sc * 8 + (blockIdx.x & 7);
    const int mT  = smr * 32 + (blockIdx.x >> 3);
    if (nT >= NT_TILES) return;

    const uint32_t* aSrc = g_x + (size_t)mT * NKC * TILE_U32;
    const uint32_t* bSrc = g_w + (size_t)nT * NKC * TILE_U32;
    const uint32_t sb = smem_u32(sm);

    float acc[4][4][4];
#pragma unroll
    for (int b = 0; b < 4; ++b)
#pragma unroll
        for (int nb = 0; nb < 4; ++nb)
#pragma unroll
            for (int i = 0; i < 4; ++i) acc[b][nb][i] = 0.0f;

    // ---- pipeline prologue: load chunks 0..STAGES-2 ----
#pragma unroll
    for (int s = 0; s < STAGES - 1; ++s) {
        const uint32_t dst = sb + s * STAGE_U32 * 4;
#pragma unroll
        for (int i = 0; i < 4; ++i) {
            const int f = i * 256 + tid;        // uint4 index, 0..1023
            const uint32_t* src = (f < 512)
                ? (aSrc + (size_t)s * TILE_U32 + f * 4)
                : (bSrc + (size_t)s * TILE_U32 + (f - 512) * 4);
            CP_ASYNC16(dst + f * 16, src);
        }
        CP_COMMIT();
    }

    int stage = 0, pf_stage = STAGES - 1;
#pragma unroll 1
    for (int kc = 0; kc < NKC; ++kc) {
        CP_WAIT2();              // chunk kc resident
        __syncthreads();         // and everyone done with stage being refilled

        // prefetch chunk kc+STAGES-1
        if (kc + STAGES - 1 < NKC) {
            const int pc = kc + STAGES - 1;
            const uint32_t dst = sb + pf_stage * STAGE_U32 * 4;
#pragma unroll
            for (int i = 0; i < 4; ++i) {
                const int f = i * 256 + tid;
                const uint32_t* src = (f < 512)
                    ? (aSrc + (size_t)pc * TILE_U32 + f * 4)
                    : (bSrc + (size_t)pc * TILE_U32 + (f - 512) * 4);
                CP_ASYNC16(dst + f * 16, src);
            }
        }
        CP_COMMIT();
        if (++pf_stage == STAGES) pf_stage = 0;

        // ---- compute chunk kc (k=32 = 2 k16-steps) ----
        const uint32_t* As = sm + stage * STAGE_U32;
        const uint32_t* Bs = As + TILE_U32;

#pragma unroll
        for (int ks = 0; ks < 2; ++ks) {
            uint4 Af[4], Bf[2];
#pragma unroll
            for (int b = 0; b < 4; ++b)
                Af[b] = *(const uint4*)
                    (As + ((wm * 8 + ks * 4 + b) * 32 + lane) * 4);
#pragma unroll
            for (int p = 0; p < 2; ++p)
                Bf[p] = *(const uint4*)
                    (Bs + ((((wn * 2 + ks) * 2 + p) * 32) + lane) * 4);

#pragma unroll
            for (int b = 0; b < 4; ++b) {
                const uint4 a = Af[b];
#pragma unroll
                for (int nb = 0; nb < 4; ++nb) {
                    const uint4 bf = Bf[nb >> 1];
                    const uint32_t b0v = (nb & 1) ? bf.z : bf.x;
                    const uint32_t b1v = (nb & 1) ? bf.w : bf.y;
                    MMA_F16(acc[b][nb], a, b0v, b1v);
                }
            }
        }
        if (++stage == STAGES) stage = 0;
    }

    // ---- epilogue: bias + store ----
    const int gid = lane >> 2, tig = lane & 3;
    const int m0 = mT * 128 + wm * 64;
    const int n0 = nT * 128 + wn * 32;
#pragma unroll
    for (int nb = 0; nb < 4; ++nb) {
        const int n = n0 + nb * 8 + tig * 2;
        const float2 bv = *(const float2*)(bias + n);
#pragma unroll
        for (int b = 0; b < 4; ++b) {
            const int mA = m0 + b * 16 + gid;
            float2 v0, v1;
            v0.x = acc[b][nb][0] + bv.x;
            v0.y = acc[b][nb][1] + bv.y;
            v1.x = acc[b][nb][2] + bv.x;
            v1.y = acc[b][nb][3] + bv.y;
            *(float2*)(out + (size_t)mA * OUT_DIM + n) = v0;
            *(float2*)(out + (size_t)(mA + 8) * OUT_DIM + n) = v1;
        }
    }
}

// ============================================================================
extern "C" void kernel_launch(void* const* d_in, const int* in_sizes, int n_in,
                              void* d_out, int out_size) {
    const float* x         = (const float*)d_in[0];
    const int*   packed    = (const int*)  d_in[1];
    const float* scales    = (const float*)d_in[2];
    const float* offsets   = (const float*)d_in[3];
    const float* inv_scale = (const float*)d_in[4];
    const float* bias      = (const float*)d_in[5];
    float*       out       = (float*)d_out;

    static bool attr_set = false;
    if (!attr_set) {
        cudaFuncSetAttribute(awq_mma_gemm,
                             cudaFuncAttributeMaxDynamicSharedMemorySize,
                             SMEM_BYTES);
        attr_set = true;
    }

    dequant_w_kernel<<<(OUT_DIM * (IN_DIM / 2)) / 1024, 256>>>(packed, scales,
                                                               offsets, inv_scale);
    prep_x_kernel<<<(M_DIM * (IN_DIM / 2)) / 1024, 256>>>(x);

    dim3 grid(256, 22);   // 8 nT x 32 mT supertiles; 2 superrows x 11 supercols
    awq_mma_gemm<<<grid, 256, SMEM_BYTES>>>(bias, out);
}

// round 7
// speedup vs baseline: 9.1520x; 1.0069x over previous
#include <cuda_runtime.h>
#include <cuda_fp16.h>
#include <cstdint>

// ============================================================================
// AWQ int4 linear via fp16 mma.sync (m16n8k16, fp32 accumulate):
//   (1) dequant W -> fp16 fragment-order tiles (smem-staged, coalesced R/W)
//   (2) round x  -> fp16 fragment-order tiles (smem-staged)
//   (3) GEMM: 128x128 CTA tiles, warp 64x32, k-chunk 64,
//       3-stage cp.async pipeline, 2 CTAs/SM, conflict-free LDS.128 loads.
// out[m][n] = sum_k x[m][k]*W[n][k] + bias[n]
// W[n][k] = (q[n][k]*scales[g]+offsets[g])*inv_scale[k], g = n*32 + k/128
// M=8192, N=11008, K=4096.
// ============================================================================

#define IN_DIM   4096
#define OUT_DIM  11008
#define M_DIM    8192
#define BKC      64                    // k per pipeline stage
#define NKC      (IN_DIM / BKC)        // 64 k-chunks
#define STAGES   3
#define TILE_U32 4096                  // one 128x64 fp16 operand tile (16KB)
#define STAGE_U32 (2 * TILE_U32)       // A tile then B tile (32KB)
#define SMEM_BYTES (STAGES * STAGE_U32 * 4)   // 98304 (96KB)
#define MT_TILES  (M_DIM / 128)        // 64
#define NT_TILES  (OUT_DIM / 128)      // 86

// Pre-tiled fp16 operands in fragment order (static scratch; no allocs).
__device__ uint32_t g_w[(size_t)NT_TILES * NKC * TILE_U32];   // 90 MB
__device__ uint32_t g_x[(size_t)MT_TILES * NKC * TILE_U32];   // 67 MB

__device__ __forceinline__ uint32_t smem_u32(const void* p) {
    uint32_t a;
    asm("{ .reg .u64 t; cvta.to.shared.u64 t, %1; cvt.u32.u64 %0, t; }"
        : "=r"(a) : "l"(p));
    return a;
}

// ---- fragment-order u32 offsets within a 4096-u32 (128 x 64 fp16) tile ----
// A (x): vec v = wm*16 + ks*4 + b  (wm: m64-half, ks: k16-step, b: m16-block)
__device__ __forceinline__ int a_u32(int mm, int kk) {
    const int wm = mm >> 6, b = (mm >> 4) & 3, row = mm & 15;
    const int gid = row & 7, hi = row >> 3;
    const int ks = kk >> 4, kk16 = kk & 15;
    const int colhi = (kk16 >> 3) & 1, tig = (kk16 >> 1) & 3;
    const int v = wm * 16 + ks * 4 + b;
    return (v * 32 + gid * 4 + tig) * 4 + hi + 2 * colhi;
}
// B (W): vec = (wn*4 + ks)*2 + p  (wn: n32-quarter, p: nb pair)
__device__ __forceinline__ int b_u32(int nn, int kk) {
    const int wn = nn >> 5, nb = (nn >> 3) & 3, gid = nn & 7;
    const int ks = kk >> 4, kk16 = kk & 15;
    const int khi = (kk16 >> 3) & 1, tig = (kk16 >> 1) & 3;
    return ((((wn * 4 + ks) * 2 + (nb >> 1)) * 32) + gid * 4 + tig) * 4
           + (nb & 1) * 2 + khi;
}

__device__ __forceinline__ uint32_t pack_h2(float lo, float hi) {
    __half2 h = __floats2half2_rn(lo, hi);   // .x = lo half
    return *(uint32_t*)&h;
}

// ============================================================================
// Prepass 1: dequant W. One block builds one 128x64 tile in smem (fragment
// order), then writes it out coalesced. Reads are 128B-coalesced per row.
// ============================================================================
__global__ __launch_bounds__(256)
void dequant_w_kernel(const int* __restrict__ packed,
                      const float* __restrict__ scales,
                      const float* __restrict__ offsets,
                      const float* __restrict__ inv) {
    __shared__ uint32_t st[TILE_U32];
    const int tile = blockIdx.x;           // nT * NKC + kc
    const int nT = tile / NKC, kc = tile % NKC;
    const int tid = threadIdx.x;
    const int r = tid >> 1, h = tid & 1;   // row 0..127, half 0..1
    const int n = nT * 128 + r;
    const int g = (n << 5) + (kc >> 1);    // 64 k's of a tile sit in one group
    const float s = __ldg(scales + g);
    const float o = __ldg(offsets + g);
    const int kbase = kc * 64 + h * 32;
    const int* src = packed + (size_t)n * 2048 + (kbase >> 1);

#pragma unroll
    for (int i = 0; i < 4; ++i) {
        const int4 u4 = *(const int4*)(src + i * 4);
        const int uv[4] = {u4.x, u4.y, u4.z, u4.w};
#pragma unroll
        for (int j = 0; j < 4; ++j) {
            const int u = uv[j];
            const int kk = h * 32 + i * 8 + j * 2;
            const int kglob = kc * 64 + kk;
            const float w0 = fmaf((float)(u & 15), s, o) * __ldg(inv + kglob);
            const float w1 = fmaf((float)((u >> 4) & 15), s, o)
                             * __ldg(inv + kglob + 1);
            st[b_u32(r, kk)] = pack_h2(w0, w1);
        }
    }
    __syncthreads();

    uint4* dst = (uint4*)(g_w + (size_t)tile * TILE_U32);
    const uint4* ss = (const uint4*)st;
#pragma unroll
    for (int i = 0; i < 4; ++i)
        dst[i * 256 + tid] = ss[i * 256 + tid];
}

// ============================================================================
// Prepass 2: x -> fp16 tiles, same smem-staged scheme.
// ============================================================================
__global__ __launch_bounds__(256)
void prep_x_kernel(const float* __restrict__ x) {
    __shared__ uint32_t st[TILE_U32];
    const int tile = blockIdx.x;           // mT * NKC + kc
    const int mT = tile / NKC, kc = tile % NKC;
    const int tid = threadIdx.x;
    const int r = tid >> 1, h = tid & 1;
    const int m = mT * 128 + r;
    const float4* src = (const float4*)(x + (size_t)m * IN_DIM + kc * 64 + h * 32);

#pragma unroll
    for (int i = 0; i < 8; ++i) {
        const float4 v = src[i];
        const int kk = h * 32 + i * 4;
        st[a_u32(r, kk)]     = pack_h2(v.x, v.y);
        st[a_u32(r, kk + 2)] = pack_h2(v.z, v.w);
    }
    __syncthreads();

    uint4* dst = (uint4*)(g_x + (size_t)tile * TILE_U32);
    const uint4* ss = (const uint4*)st;
#pragma unroll
    for (int i = 0; i < 4; ++i)
        dst[i * 256 + tid] = ss[i * 256 + tid];
}

// ============================================================================
// Main GEMM
// ============================================================================
#define MMA_F16(c, a, b0v, b1v)                                                \
    asm volatile("mma.sync.aligned.m16n8k16.row.col.f32.f16.f16.f32 "          \
        "{%0,%1,%2,%3}, {%4,%5,%6,%7}, {%8,%9}, {%0,%1,%2,%3};"                \
        : "+f"((c)[0]), "+f"((c)[1]), "+f"((c)[2]), "+f"((c)[3])               \
        : "r"((a).x), "r"((a).y), "r"((a).z), "r"((a).w),                      \
          "r"(b0v), "r"(b1v))

#define CP_ASYNC16(dst, src)                                                   \
    asm volatile("cp.async.cg.shared.global [%0], [%1], 16;"                   \
                 :: "r"(dst), "l"(src) : "memory")
#define CP_COMMIT()  asm volatile("cp.async.commit_group;" ::: "memory")
#define CP_WAIT1()   asm volatile("cp.async.wait_group 1;" ::: "memory")

__global__ __launch_bounds__(256, 2)
void awq_mma_gemm(const float* __restrict__ bias, float* __restrict__ out) {
    extern __shared__ uint32_t sm[];
    const int tid  = threadIdx.x;
    const int wid  = tid >> 5;
    const int lane = tid & 31;
    const int wm   = wid >> 2;      // 0..1 (m 64-half)
    const int wn   = wid & 3;       // 0..3 (n 32-quarter)

    // supertile raster: grid(256, 22); x: 8 nT x 32 mT inside a supertile
    const int sc  = blockIdx.y % 11;      // supercolumn (8 nT each)
    const int smr = blockIdx.y / 11;      // superrow (32 mT each)
    const int nT  = sc * 8 + (blockIdx.x & 7);
    const int mT  = smr * 32 + (blockIdx.x >> 3);
    if (nT >= NT_TILES) return;

    const uint32_t* aSrc = g_x + (size_t)mT * NKC * TILE_U32;
    const uint32_t* bSrc = g_w + (size_t)nT * NKC * TILE_U32;
    const uint32_t sb = smem_u32(sm);

    float acc[4][4][4];
#pragma unroll
    for (int b = 0; b < 4; ++b)
#pragma unroll
        for (int nb = 0; nb < 4; ++nb)
#pragma unroll
            for (int i = 0; i < 4; ++i) acc[b][nb][i] = 0.0f;

    // ---- pipeline prologue: load chunks 0..STAGES-2 ----
#pragma unroll
    for (int s = 0; s < STAGES - 1; ++s) {
        const uint32_t dst = sb + s * STAGE_U32 * 4;
#pragma unroll
        for (int i = 0; i < 8; ++i) {
            const int f = i * 256 + tid;        // uint4 index, 0..2047
            const uint32_t* src = (f < 1024)
                ? (aSrc + (size_t)s * TILE_U32 + f * 4)
                : (bSrc + (size_t)s * TILE_U32 + (f - 1024) * 4);
            CP_ASYNC16(dst + f * 16, src);
        }
        CP_COMMIT();
    }

    int stage = 0, pf_stage = STAGES - 1;
#pragma unroll 1
    for (int kc = 0; kc < NKC; ++kc) {
        CP_WAIT1();              // chunk kc resident
        __syncthreads();         // and everyone done with stage being refilled

        // prefetch chunk kc+STAGES-1
        if (kc + STAGES - 1 < NKC) {
            const int pc = kc + STAGES - 1;
            const uint32_t dst = sb + pf_stage * STAGE_U32 * 4;
#pragma unroll
            for (int i = 0; i < 8; ++i) {
                const int f = i * 256 + tid;
                const uint32_t* src = (f < 1024)
                    ? (aSrc + (size_t)pc * TILE_U32 + f * 4)
                    : (bSrc + (size_t)pc * TILE_U32 + (f - 1024) * 4);
                CP_ASYNC16(dst + f * 16, src);
            }
        }
        CP_COMMIT();
        if (++pf_stage == STAGES) pf_stage = 0;

        // ---- compute chunk kc (k=64 = 4 k16-steps) ----
        const uint32_t* As = sm + stage * STAGE_U32;
        const uint32_t* Bs = As + TILE_U32;

#pragma unroll
        for (int ks = 0; ks < 4; ++ks) {
            uint4 Af[4], Bf[2];
#pragma unroll
            for (int b = 0; b < 4; ++b)
                Af[b] = *(const uint4*)
                    (As + ((wm * 16 + ks * 4 + b) * 32 + lane) * 4);
#pragma unroll
            for (int p = 0; p < 2; ++p)
                Bf[p] = *(const uint4*)
                    (Bs + ((((wn * 4 + ks) * 2 + p) * 32) + lane) * 4);

#pragma unroll
            for (int b = 0; b < 4; ++b) {
                const uint4 a = Af[b];
#pragma unroll
                for (int nb = 0; nb < 4; ++nb) {
                    const uint4 bf = Bf[nb >> 1];
                    const uint32_t b0v = (nb & 1) ? bf.z : bf.x;
                    const uint32_t b1v = (nb & 1) ? bf.w : bf.y;
                    MMA_F16(acc[b][nb], a, b0v, b1v);
                }
            }
        }
        if (++stage == STAGES) stage = 0;
    }

    // ---- epilogue: bias + store ----
    const int gid = lane >> 2, tig = lane & 3;
    const int m0 = mT * 128 + wm * 64;
    const int n0 = nT * 128 + wn * 32;
#pragma unroll
    for (int nb = 0; nb < 4; ++nb) {
        const int n = n0 + nb * 8 + tig * 2;
        const float2 bv = *(const float2*)(bias + n);
#pragma unroll
        for (int b = 0; b < 4; ++b) {
            const int mA = m0 + b * 16 + gid;
            float2 v0, v1;
            v0.x = acc[b][nb][0] + bv.x;
            v0.y = acc[b][nb][1] + bv.y;
            v1.x = acc[b][nb][2] + bv.x;
            v1.y = acc[b][nb][3] + bv.y;
            *(float2*)(out + (size_t)mA * OUT_DIM + n) = v0;
            *(float2*)(out + (size_t)(mA + 8) * OUT_DIM + n) = v1;
        }
    }
}

// ============================================================================
extern "C" void kernel_launch(void* const* d_in, const int* in_sizes, int n_in,
                              void* d_out, int out_size) {
    const float* x         = (const float*)d_in[0];
    const int*   packed    = (const int*)  d_in[1];
    const float* scales    = (const float*)d_in[2];
    const float* offsets   = (const float*)d_in[3];
    const float* inv_scale = (const float*)d_in[4];
    const float* bias      = (const float*)d_in[5];
    float*       out       = (float*)d_out;

    static bool attr_set = false;
    if (!attr_set) {
        cudaFuncSetAttribute(awq_mma_gemm,
                             cudaFuncAttributeMaxDynamicSharedMemorySize,
                             SMEM_BYTES);
        attr_set = true;
    }

    dequant_w_kernel<<<NT_TILES * NKC, 256>>>(packed, scales, offsets, inv_scale);
    prep_x_kernel<<<MT_TILES * NKC, 256>>>(x);

    dim3 grid(256, 22);   // 8 nT x 32 mT supertiles; 2 superrows x 11 supercols
    awq_mma_gemm<<<grid, 256, SMEM_BYTES>>>(bias, out);
}